// round 15
// baseline (speedup 1.0000x reference)
#include <cuda_runtime.h>
#include <math.h>

// Problem constants
#define NB    16      // batch
#define CDIM  512     // channels
#define CB    64      // bottleneck channels
#define NPIX  4096    // H*W

// -------- device scratch (allocation-free rule: __device__ globals) --------
__device__ float g_qkv[(size_t)NB * 192 * NPIX];   // [b][m 0..191][n]; q=0..63,k=64..127,v=128..191
__device__ float g_lpart[NB * 8 * 64 * 64];        // logits partials over 8 n-splits
__device__ float g_attn[NB * 64 * 64];             // softmax(logits)
__device__ float g_w2[NB * 512 * 64];              // W2 = w_o @ attn  per batch

// ============================================================================
// Kernel A: QKV = W @ X  (+bias).  Per (batch, which∈{q,k,v}) a 64x4096 GEMM, K=512.
// BM=64, BN=128, BK=16, 128 threads, 8x8 register tile per thread.
// ============================================================================
__global__ __launch_bounds__(128) void qkv_gemm(
    const float* __restrict__ x,
    const float* __restrict__ wq, const float* __restrict__ bq,
    const float* __restrict__ wk, const float* __restrict__ bk,
    const float* __restrict__ wv, const float* __restrict__ bv)
{
    const int b     = blockIdx.z;
    const int which = blockIdx.y;                 // 0=q,1=k,2=v
    const float* W    = (which == 0) ? wq : (which == 1) ? wk : wv;
    const float* bias = (which == 0) ? bq : (which == 1) ? bk : bv;
    const int n0 = blockIdx.x * 128;
    const float* X = x + (size_t)b * CDIM * NPIX;
    float* outp = g_qkv + (size_t)b * 192 * NPIX + (size_t)which * 64 * NPIX;

    __shared__ __align__(16) float As[16][64];    // [k][m]
    __shared__ __align__(16) float Bs[16][128];   // [k][n]

    const int tid = threadIdx.x;
    const int tm  = tid >> 4;    // 0..7  -> rows tm*8..tm*8+7
    const int tn  = tid & 15;    // 0..15 -> cols tn*8..tn*8+7

    float acc[8][8];
    #pragma unroll
    for (int i = 0; i < 8; i++)
        #pragma unroll
        for (int j = 0; j < 8; j++) acc[i][j] = 0.f;

    for (int k0 = 0; k0 < CDIM; k0 += 16) {
        // load A tile 64x16: 256 float4 slots, 2 per thread. W row-major [64][512].
        #pragma unroll
        for (int r = 0; r < 2; ++r) {
            int id   = tid + r * 128;             // 0..255
            int row  = id >> 2;                   // m 0..63
            int col4 = (id & 3) << 2;             // k offset 0,4,8,12
            float4 v4 = *(const float4*)(W + (size_t)row * CDIM + k0 + col4);
            As[col4 + 0][row] = v4.x;
            As[col4 + 1][row] = v4.y;
            As[col4 + 2][row] = v4.z;
            As[col4 + 3][row] = v4.w;
        }
        // load B tile 16x128: 512 float4 slots, 4 per thread. X rows contiguous in n.
        #pragma unroll
        for (int r = 0; r < 4; ++r) {
            int id  = tid + r * 128;              // 0..511
            int row = id >> 5;                    // k 0..15
            int col = (id & 31) << 2;             // n offset
            *(float4*)&Bs[row][col] =
                *(const float4*)(X + (size_t)(k0 + row) * NPIX + n0 + col);
        }
        __syncthreads();

        #pragma unroll
        for (int k = 0; k < 16; ++k) {
            float a[8], bb[8];
            *(float4*)&a[0]  = *(const float4*)&As[k][tm * 8];
            *(float4*)&a[4]  = *(const float4*)&As[k][tm * 8 + 4];
            *(float4*)&bb[0] = *(const float4*)&Bs[k][tn * 8];
            *(float4*)&bb[4] = *(const float4*)&Bs[k][tn * 8 + 4];
            #pragma unroll
            for (int i = 0; i < 8; i++)
                #pragma unroll
                for (int j = 0; j < 8; j++)
                    acc[i][j] = fmaf(a[i], bb[j], acc[i][j]);
        }
        __syncthreads();
    }

    // epilogue: +bias, store
    #pragma unroll
    for (int i = 0; i < 8; i++) {
        int m = tm * 8 + i;
        float bi = bias[m];
        float* orow = outp + (size_t)m * NPIX + n0 + tn * 8;
        float4 o0 = make_float4(acc[i][0] + bi, acc[i][1] + bi, acc[i][2] + bi, acc[i][3] + bi);
        float4 o1 = make_float4(acc[i][4] + bi, acc[i][5] + bi, acc[i][6] + bi, acc[i][7] + bi);
        *(float4*)(orow)     = o0;
        *(float4*)(orow + 4) = o1;
    }
}

// ============================================================================
// Kernel B: logits partials. grid (8 splits, 16 batches), 256 threads.
// L[c][d] += sum_n q[c][n]*k[d][n] over a 512-wide n-split.
// ============================================================================
__global__ __launch_bounds__(256) void logits_partial()
{
    const int s = blockIdx.x;
    const int b = blockIdx.y;
    const float* q  = g_qkv + (size_t)b * 192 * NPIX;
    const float* kk = q + (size_t)64 * NPIX;
    const int n0 = s * 512;

    __shared__ __align__(16) float qs[32][68];   // [n][c], padded
    __shared__ __align__(16) float ks[32][68];

    const int tid = threadIdx.x;
    const int tc  = tid >> 4;    // 0..15 -> c group
    const int td  = tid & 15;    // 0..15 -> d group

    float acc[4][4];
    #pragma unroll
    for (int i = 0; i < 4; i++)
        #pragma unroll
        for (int j = 0; j < 4; j++) acc[i][j] = 0.f;

    for (int nt = 0; nt < 512; nt += 32) {
        #pragma unroll
        for (int r = 0; r < 2; ++r) {
            int id = tid + r * 256;               // 0..511
            int c  = id >> 3;                     // 0..63
            int nn = (id & 7) << 2;               // 0..28
            float4 qv = *(const float4*)(q  + (size_t)c * NPIX + n0 + nt + nn);
            float4 kv = *(const float4*)(kk + (size_t)c * NPIX + n0 + nt + nn);
            qs[nn + 0][c] = qv.x; qs[nn + 1][c] = qv.y; qs[nn + 2][c] = qv.z; qs[nn + 3][c] = qv.w;
            ks[nn + 0][c] = kv.x; ks[nn + 1][c] = kv.y; ks[nn + 2][c] = kv.z; ks[nn + 3][c] = kv.w;
        }
        __syncthreads();
        #pragma unroll
        for (int n = 0; n < 32; ++n) {
            float a[4], bb[4];
            *(float4*)a  = *(const float4*)&qs[n][tc * 4];
            *(float4*)bb = *(const float4*)&ks[n][td * 4];
            #pragma unroll
            for (int i = 0; i < 4; i++)
                #pragma unroll
                for (int j = 0; j < 4; j++)
                    acc[i][j] = fmaf(a[i], bb[j], acc[i][j]);
        }
        __syncthreads();
    }

    float* lp = g_lpart + (size_t)(b * 8 + s) * 64 * 64;
    #pragma unroll
    for (int i = 0; i < 4; i++)
        #pragma unroll
        for (int j = 0; j < 4; j++)
            lp[(size_t)(tc * 4 + i) * 64 + td * 4 + j] = acc[i][j];
}

// ============================================================================
// Kernel B2: reduce partials + row softmax. grid 16, 64 threads (thread = row c).
// ============================================================================
__global__ __launch_bounds__(64) void softmax_k()
{
    const int b = blockIdx.x;
    const int c = threadIdx.x;

    float v[64];
    #pragma unroll
    for (int d = 0; d < 64; ++d) v[d] = 0.f;
    #pragma unroll
    for (int s = 0; s < 8; ++s) {
        const float* p = g_lpart + ((size_t)(b * 8 + s) * 64 + c) * 64;
        #pragma unroll
        for (int d = 0; d < 64; ++d) v[d] += p[d];
    }
    float mx = v[0];
    #pragma unroll
    for (int d = 1; d < 64; ++d) mx = fmaxf(mx, v[d]);
    float sum = 0.f;
    #pragma unroll
    for (int d = 0; d < 64; ++d) { v[d] = expf(v[d] - mx); sum += v[d]; }
    float inv = 1.f / sum;
    float* ap = g_attn + ((size_t)b * 64 + c) * 64;
    #pragma unroll
    for (int d = 0; d < 64; ++d) ap[d] = v[d] * inv;
}

// ============================================================================
// Kernel D: W2[b] = w_o @ attn[b]   (512x64 = [512,64]@[64,64]).
// grid (8 m-chunks of 64, 16 batches), 256 threads; thread: 1 m-row x 16 d's.
// ============================================================================
__global__ __launch_bounds__(256) void w2_kernel(const float* __restrict__ wo)
{
    const int b  = blockIdx.y;
    const int m0 = blockIdx.x * 64;
    __shared__ __align__(16) float attn_s[64][64];

    const int tid = threadIdx.x;
    const float4* ap = (const float4*)(g_attn + (size_t)b * 64 * 64);
    #pragma unroll
    for (int r = 0; r < 4; ++r)
        ((float4*)attn_s)[tid + r * 256] = ap[tid + r * 256];
    __syncthreads();

    const int m  = m0 + (tid >> 2);
    const int d0 = (tid & 3) * 16;
    const float* wrow = wo + (size_t)m * 64;

    float acc[16];
    #pragma unroll
    for (int j = 0; j < 16; j++) acc[j] = 0.f;
    #pragma unroll
    for (int c = 0; c < 64; ++c) {
        float w = __ldg(wrow + c);
        #pragma unroll
        for (int j = 0; j < 16; j++)
            acc[j] = fmaf(w, attn_s[c][d0 + j], acc[j]);
    }
    float* o = g_w2 + ((size_t)b * 512 + m) * 64 + d0;
    #pragma unroll
    for (int j = 0; j < 16; j += 4)
        *(float4*)(o + j) = make_float4(acc[j], acc[j + 1], acc[j + 2], acc[j + 3]);
}

// ============================================================================
// Kernel C: out = gamma * (W2 @ v + b_o) + x.  Per batch: [512,64]@[64,4096].
// BM=64, BN=128, BK=16 (4 k-iters), 128 threads, 8x8 tile. Fused epilogue.
// ============================================================================
__global__ __launch_bounds__(128) void final_gemm(
    const float* __restrict__ x,
    const float* __restrict__ bo,
    const float* __restrict__ gamma,
    float* __restrict__ out)
{
    const int b  = blockIdx.z;
    const int m0 = blockIdx.y * 64;
    const int n0 = blockIdx.x * 128;
    const float* A = g_w2 + (size_t)b * 512 * 64;                   // [512][64]
    const float* V = g_qkv + (size_t)b * 192 * NPIX + (size_t)128 * NPIX;  // [64][4096]

    __shared__ __align__(16) float As[16][64];
    __shared__ __align__(16) float Bs[16][128];

    const int tid = threadIdx.x;
    const int tm  = tid >> 4;
    const int tn  = tid & 15;

    float acc[8][8];
    #pragma unroll
    for (int i = 0; i < 8; i++)
        #pragma unroll
        for (int j = 0; j < 8; j++) acc[i][j] = 0.f;

    #pragma unroll
    for (int k0 = 0; k0 < 64; k0 += 16) {
        #pragma unroll
        for (int r = 0; r < 2; ++r) {
            int id   = tid + r * 128;
            int row  = id >> 2;                   // local m 0..63
            int col4 = (id & 3) << 2;
            float4 v4 = *(const float4*)(A + (size_t)(m0 + row) * 64 + k0 + col4);
            As[col4 + 0][row] = v4.x;
            As[col4 + 1][row] = v4.y;
            As[col4 + 2][row] = v4.z;
            As[col4 + 3][row] = v4.w;
        }
        #pragma unroll
        for (int r = 0; r < 4; ++r) {
            int id  = tid + r * 128;
            int row = id >> 5;
            int col = (id & 31) << 2;
            *(float4*)&Bs[row][col] =
                *(const float4*)(V + (size_t)(k0 + row) * NPIX + n0 + col);
        }
        __syncthreads();
        #pragma unroll
        for (int k = 0; k < 16; ++k) {
            float a[8], bb[8];
            *(float4*)&a[0]  = *(const float4*)&As[k][tm * 8];
            *(float4*)&a[4]  = *(const float4*)&As[k][tm * 8 + 4];
            *(float4*)&bb[0] = *(const float4*)&Bs[k][tn * 8];
            *(float4*)&bb[4] = *(const float4*)&Bs[k][tn * 8 + 4];
            #pragma unroll
            for (int i = 0; i < 8; i++)
                #pragma unroll
                for (int j = 0; j < 8; j++)
                    acc[i][j] = fmaf(a[i], bb[j], acc[i][j]);
        }
        __syncthreads();
    }

    const float g = __ldg(gamma);
    #pragma unroll
    for (int i = 0; i < 8; i++) {
        int m = m0 + tm * 8 + i;
        float bias = __ldg(bo + m);
        size_t base = ((size_t)b * 512 + m) * NPIX + n0 + tn * 8;
        float4 x0 = *(const float4*)(x + base);
        float4 x1 = *(const float4*)(x + base + 4);
        float4 o0, o1;
        o0.x = fmaf(g, acc[i][0] + bias, x0.x);
        o0.y = fmaf(g, acc[i][1] + bias, x0.y);
        o0.z = fmaf(g, acc[i][2] + bias, x0.z);
        o0.w = fmaf(g, acc[i][3] + bias, x0.w);
        o1.x = fmaf(g, acc[i][4] + bias, x1.x);
        o1.y = fmaf(g, acc[i][5] + bias, x1.y);
        o1.z = fmaf(g, acc[i][6] + bias, x1.z);
        o1.w = fmaf(g, acc[i][7] + bias, x1.w);
        *(float4*)(out + base)     = o0;
        *(float4*)(out + base + 4) = o1;
    }
}

// ============================================================================
// launch
// ============================================================================
extern "C" void kernel_launch(void* const* d_in, const int* in_sizes, int n_in,
                              void* d_out, int out_size)
{
    const float* x   = (const float*)d_in[0];   // [16,512,64,64]
    const float* w_q = (const float*)d_in[1];   // [64,512]
    const float* b_q = (const float*)d_in[2];   // [64]
    const float* w_k = (const float*)d_in[3];
    const float* b_k = (const float*)d_in[4];
    const float* w_v = (const float*)d_in[5];
    const float* b_v = (const float*)d_in[6];
    const float* w_o = (const float*)d_in[7];   // [512,64]
    const float* b_o = (const float*)d_in[8];   // [512]
    const float* gm  = (const float*)d_in[9];   // [1]
    float* out = (float*)d_out;

    // 1) QKV projections
    qkv_gemm<<<dim3(NPIX / 128, 3, NB), 128>>>(x, w_q, b_q, w_k, b_k, w_v, b_v);
    // 2) channel-attention logits (8-way n-split partials)
    logits_partial<<<dim3(8, NB), 256>>>();
    // 3) reduce + softmax
    softmax_k<<<NB, 64>>>();
    // 4) W2 = w_o @ attn
    w2_kernel<<<dim3(8, NB), 256>>>(w_o);
    // 5) out = gamma*(W2 @ v + b_o) + x
    final_gemm<<<dim3(NPIX / 128, 512 / 64, NB), 128>>>(x, b_o, gm, out);
}